// round 9
// baseline (speedup 1.0000x reference)
#include <cuda_runtime.h>
#include <cuda_bf16.h>

// x: [64, 133, 64, 64] fp32 -> out [64, 133, 32, 32]
constexpr int B  = 64;
constexpr int C  = 133;
constexpr int Cm = 128;
constexpr int H  = 64;
constexpr int W  = 64;
constexpr int Ho = 32;
constexpr int Wo = 32;
constexpr int HW = H * W;
constexpr int HoWo = Ho * Wo;

constexpr int NWARPS  = 16;
constexpr int CPW     = Cm / NWARPS;   // 8 pooled channels per warp
constexpr int NTILES  = B * Ho;        // 2048 (b, ho) tiles
constexpr int NBLOCKS = 456;           // ~3 per SM, persistent

// Channels [0, RESIDENT_CH) are pinned in L2 across graph replays (evict_last):
// 72 MB input + ~35 MB output + 5 MB stat channels ~= 112 MB < 126 MB L2.
constexpr int RESIDENT_CH = 72;        // multiple of CPW (whole warps)

__device__ int g_ticket;

__global__ void reset_ticket_kernel() { g_ticket = NBLOCKS; }

__device__ __forceinline__ float4 ldcs4(const float* p) {
    return __ldcs((const float4*)p);   // streaming: evict-first
}

__device__ __forceinline__ float4 ldel4(const float* p, unsigned long long pol) {
    float4 v;                          // L2-resident: evict-last via cache-hint policy
    asm("ld.global.L2::cache_hint.v4.f32 {%0,%1,%2,%3}, [%4], %5;"
        : "=f"(v.x), "=f"(v.y), "=f"(v.z), "=f"(v.w) : "l"(p), "l"(pol));
    return v;
}

__global__ __launch_bounds__(NWARPS * 32, 3)
void spatial_maxpool_stats_kernel(const float* __restrict__ x,
                                  float* __restrict__ out) {
    const int lane = threadIdx.x & 31;
    const int warp = threadIdx.x >> 5;
    const int l16  = lane & 15;
    const int half = lane >> 4;

    __shared__ unsigned s_cnt[Wo];
    __shared__ float4   s_stat[2][5][32];   // [parity][stat chan][row*16 + col4]
    __shared__ int      s_next;

    const bool resident = (warp * CPW) < RESIDENT_CH;  // warp-uniform

    unsigned long long pol;
    asm("createpolicy.fractional.L2::evict_last.b64 %0, 1.0;" : "=l"(pol));

    int tile = blockIdx.x;
    int par  = 0;

    while (tile < NTILES) {
        const int b  = tile >> 5;
        const int ho = tile & 31;
        const float* xb = x   + (size_t)b * C * HW;
        float*       ob = out + (size_t)b * C * HoWo;

        // ---- stat-channel prefetch: warps 0-4 -> smem via cp.async
        if (warp < 5) {
            const float* src = xb + (size_t)(Cm + warp) * HW
                             + (2 * ho + half) * W + 4 * l16;
            unsigned dst = (unsigned)__cvta_generic_to_shared(&s_stat[par][warp][lane]);
            asm volatile("cp.async.cg.shared.global [%0], [%1], 16;\n"
                         "cp.async.commit_group;\n" :: "r"(dst), "l"(src));
        }

        // ---- pooled group 0 loads (4 x LDG.128 per thread)
        const int ch0 = warp * CPW + half;
        const float* pc = xb + (size_t)ch0 * HW + (2 * ho) * W + 4 * l16;
        float*       po = ob + (size_t)ch0 * HoWo + ho * Wo + 2 * l16;

        float4 t0[2], u0[2];
        if (resident) {
#pragma unroll
            for (int k = 0; k < 2; k++) {
                const float* p = pc + (size_t)(2 * k) * HW;
                t0[k] = ldel4(p, pol);
                u0[k] = ldel4(p + W, pol);
            }
        } else {
#pragma unroll
            for (int k = 0; k < 2; k++) {
                const float* p = pc + (size_t)(2 * k) * HW;
                t0[k] = ldcs4(p);
                u0[k] = ldcs4(p + W);
            }
        }

        // ---- ticket prefetch + count init (overlap with load latency)
        if (threadIdx.x == 0) s_next = atomicAdd(&g_ticket, 1);
        if (threadIdx.x < Wo) s_cnt[threadIdx.x] = 0u;
        __syncthreads();   // sync1: counts zeroed, s_next written

        // ---- pooled group 1 loads in flight while computing group 0
        float4 t1[2], u1[2];
        if (resident) {
#pragma unroll
            for (int k = 0; k < 2; k++) {
                const float* p = pc + (size_t)(4 + 2 * k) * HW;
                t1[k] = ldel4(p, pol);
                u1[k] = ldel4(p + W, pol);
            }
        } else {
#pragma unroll
            for (int k = 0; k < 2; k++) {
                const float* p = pc + (size_t)(4 + 2 * k) * HW;
                t1[k] = ldcs4(p);
                u1[k] = ldcs4(p + W);
            }
        }
        const int next_tile = s_next;

        unsigned cnt0 = 0, cnt1 = 0;  // packed 4x8-bit argmax counts
#pragma unroll
        for (int g = 0; g < 2; g++) {
#pragma unroll
            for (int k = 0; k < 2; k++) {
                float4 t = g ? t1[k] : t0[k];
                float4 u = g ? u1[k] : u0[k];
                // window A: (t.x t.y / u.x u.y), B: (t.z t.w / u.z u.w)
                // first-occurrence argmax: later position wins only strictly
                float mtA = fmaxf(t.x, t.y); int itA = (t.y > t.x) ? 1 : 0;
                float mbA = fmaxf(u.x, u.y); int ibA = (u.y > u.x) ? 3 : 2;
                float mA  = fmaxf(mtA, mbA); int iA  = (mbA > mtA) ? ibA : itA;

                float mtB = fmaxf(t.z, t.w); int itB = (t.w > t.z) ? 1 : 0;
                float mbB = fmaxf(u.z, u.w); int ibB = (u.w > u.z) ? 3 : 2;
                float mB  = fmaxf(mtB, mbB); int iB  = (mbB > mtB) ? ibB : itB;

                float2 st; st.x = mA; st.y = mB;
                *(float2*)(po + (size_t)(g * 4 + 2 * k) * HoWo) = st;
                cnt0 += 1u << (8 * iA);
                cnt1 += 1u << (8 * iB);
            }
        }
        atomicAdd(&s_cnt[2 * l16],     cnt0);
        atomicAdd(&s_cnt[2 * l16 + 1], cnt1);

        asm volatile("cp.async.wait_group 0;" ::: "memory");
        __syncthreads();   // sync2: counts final, stat smem ready

        // ---- epilogue: warp 0 computes the 5 stat channels from smem
        if (warp == 0) {
            const int wo = lane;
            const int e  = wo & 1;            // element pair within float4
            float s0[5], s1[5], s2[5], s3[5];
#pragma unroll
            for (int j = 0; j < 5; j++) {
                float4 r0 = s_stat[par][j][wo >> 1];        // row 2ho
                float4 r1 = s_stat[par][j][16 + (wo >> 1)]; // row 2ho+1
                s0[j] = e ? r0.z : r0.x;
                s1[j] = e ? r0.w : r0.y;
                s2[j] = e ? r1.z : r1.x;
                s3[j] = e ? r1.w : r1.y;
            }
            const unsigned cc = s_cnt[wo];
            const float inv = 1.0f / (float)Cm;
            const float w0 = (float)( cc        & 255u) * inv;
            const float w1 = (float)((cc >>  8) & 255u) * inv;
            const float w2 = (float)((cc >> 16) & 255u) * inv;
            const float w3 = (float)((cc >> 24) & 255u) * inv;

            const float mean0 = s0[0]*w0 + s1[0]*w1 + s2[0]*w2 + s3[0]*w3;
            const float mean1 = s0[1]*w0 + s1[1]*w1 + s2[1]*w2 + s3[1]*w3;

            float var0 = s0[2]*w0 + s1[2]*w1 + s2[2]*w2 + s3[2]*w3;
            float var1 = s0[3]*w0 + s1[3]*w1 + s2[3]*w2 + s3[3]*w3;
            float cov  = s0[4]*w0 + s1[4]*w1 + s2[4]*w2 + s3[4]*w3;

            const float d00 = s0[0]-mean0, d10 = s1[0]-mean0, d20 = s2[0]-mean0, d30 = s3[0]-mean0;
            const float d01 = s0[1]-mean1, d11 = s1[1]-mean1, d21 = s2[1]-mean1, d31 = s3[1]-mean1;
            var0 += d00*d00*w0 + d10*d10*w1 + d20*d20*w2 + d30*d30*w3;
            var1 += d01*d01*w0 + d11*d11*w1 + d21*d21*w2 + d31*d31*w3;
            cov  += d00*d01*w0 + d10*d11*w1 + d20*d21*w2 + d30*d31*w3;

            const size_t base = (size_t)Cm * HoWo + ho * Wo + wo;
            ob[base           ] = mean0;
            ob[base +     HoWo] = mean1;
            ob[base + 2 * HoWo] = var0;
            ob[base + 3 * HoWo] = var1;
            ob[base + 4 * HoWo] = cov;
        }

        tile = next_tile;
        par ^= 1;
    }
}

extern "C" void kernel_launch(void* const* d_in, const int* in_sizes, int n_in,
                              void* d_out, int out_size) {
    const float* x = (const float*)d_in[0];
    float* out = (float*)d_out;
    reset_ticket_kernel<<<1, 1>>>();
    spatial_maxpool_stats_kernel<<<NBLOCKS, NWARPS * 32>>>(x, out);
}

// round 10
// speedup vs baseline: 1.0908x; 1.0908x over previous
#include <cuda_runtime.h>
#include <cuda_bf16.h>

// x: [64, 133, 64, 64] fp32 -> out [64, 133, 32, 32]
constexpr int B  = 64;
constexpr int C  = 133;
constexpr int Cm = 128;
constexpr int H  = 64;
constexpr int W  = 64;
constexpr int Ho = 32;
constexpr int Wo = 32;
constexpr int HW = H * W;
constexpr int HoWo = Ho * Wo;

constexpr int NWARPS  = 16;
constexpr int CPW     = Cm / NWARPS;   // 8 pooled channels per warp
constexpr int NTILES  = B * Ho;        // 2048 (b, ho) tiles
constexpr int NBLOCKS = 456;           // ~3 per SM, persistent

// Self-resetting work queue: single graph node, deterministic across replays.
__device__ int g_ticket = NBLOCKS;
__device__ int g_done   = 0;

__device__ __forceinline__ float4 ldcs4(const float* p) {
    return __ldcs((const float4*)p);   // streaming: evict-first
}

__global__ __launch_bounds__(NWARPS * 32, 3)
void spatial_maxpool_stats_kernel(const float* __restrict__ x,
                                  float* __restrict__ out) {
    const int lane = threadIdx.x & 31;
    const int warp = threadIdx.x >> 5;
    const int l16  = lane & 15;
    const int half = lane >> 4;

    __shared__ unsigned s_cnt[2][Wo];       // parity double-buffered counts
    __shared__ float4   s_stat[2][5][32];   // [parity][stat chan][row*16 + col4]
    __shared__ int      s_next[2];

    if (threadIdx.x < 64) s_cnt[threadIdx.x >> 5][threadIdx.x & 31] = 0u;
    __syncthreads();

    int tile = blockIdx.x;
    int par  = 0;

    while (tile < NTILES) {
        const int b  = tile >> 5;
        const int ho = tile & 31;
        const float* xb = x   + (size_t)b * C * HW;
        float*       ob = out + (size_t)b * C * HoWo;

        // ---- stat-channel prefetch: warps 0-4 -> smem via cp.async
        if (warp < 5) {
            const float* src = xb + (size_t)(Cm + warp) * HW
                             + (2 * ho + half) * W + 4 * l16;
            unsigned dst = (unsigned)__cvta_generic_to_shared(&s_stat[par][warp][lane]);
            asm volatile("cp.async.cg.shared.global [%0], [%1], 16;\n"
                         "cp.async.commit_group;\n" :: "r"(dst), "l"(src));
        }

        // ---- pooled group 0 loads (4 x LDG.128 per thread, evict-first)
        const int ch0 = warp * CPW + half;
        const float* pc = xb + (size_t)ch0 * HW + (2 * ho) * W + 4 * l16;
        float*       po = ob + (size_t)ch0 * HoWo + ho * Wo + 2 * l16;

        float4 t0[2], u0[2];
#pragma unroll
        for (int k = 0; k < 2; k++) {
            const float* p = pc + (size_t)(2 * k) * HW;
            t0[k] = ldcs4(p);
            u0[k] = ldcs4(p + W);
        }

        // ---- ticket prefetch (published in parity slot; read after the barrier)
        if (threadIdx.x == 0) s_next[par] = atomicAdd(&g_ticket, 1);

        // ---- pooled group 1 loads
        float4 t1[2], u1[2];
#pragma unroll
        for (int k = 0; k < 2; k++) {
            const float* p = pc + (size_t)(4 + 2 * k) * HW;
            t1[k] = ldcs4(p);
            u1[k] = ldcs4(p + W);
        }

        unsigned cnt0 = 0, cnt1 = 0;  // packed 4x8-bit argmax counts
#pragma unroll
        for (int g = 0; g < 2; g++) {
#pragma unroll
            for (int k = 0; k < 2; k++) {
                float4 t = g ? t1[k] : t0[k];
                float4 u = g ? u1[k] : u0[k];
                // window A: (t.x t.y / u.x u.y), B: (t.z t.w / u.z u.w)
                // first-occurrence argmax: later position wins only strictly
                float mtA = fmaxf(t.x, t.y); int itA = (t.y > t.x) ? 1 : 0;
                float mbA = fmaxf(u.x, u.y); int ibA = (u.y > u.x) ? 3 : 2;
                float mA  = fmaxf(mtA, mbA); int iA  = (mbA > mtA) ? ibA : itA;

                float mtB = fmaxf(t.z, t.w); int itB = (t.w > t.z) ? 1 : 0;
                float mbB = fmaxf(u.z, u.w); int ibB = (u.w > u.z) ? 3 : 2;
                float mB  = fmaxf(mtB, mbB); int iB  = (mbB > mtB) ? ibB : itB;

                float2 st; st.x = mA; st.y = mB;
                *(float2*)(po + (size_t)(g * 4 + 2 * k) * HoWo) = st;
                cnt0 += 1u << (8 * iA);
                cnt1 += 1u << (8 * iB);
            }
        }
        atomicAdd(&s_cnt[par][2 * l16],     cnt0);
        atomicAdd(&s_cnt[par][2 * l16 + 1], cnt1);

        asm volatile("cp.async.wait_group 0;" ::: "memory");
        __syncthreads();   // single per-tile barrier: counts/stats/ticket published

        const int next_tile = s_next[par];

        // ---- epilogue: warp 0 computes the 5 stat channels from smem.
        // It re-zeroes s_cnt[par]; buffer reused 2 tiles later, ordered by the
        // intervening tile's barrier. Other warps roll straight into next tile.
        if (warp == 0) {
            const int wo = lane;
            const unsigned cc = s_cnt[par][wo];
            s_cnt[par][wo] = 0u;

            const int e = wo & 1;             // element pair within float4
            float s0[5], s1[5], s2[5], s3[5];
#pragma unroll
            for (int j = 0; j < 5; j++) {
                float4 r0 = s_stat[par][j][wo >> 1];        // row 2ho
                float4 r1 = s_stat[par][j][16 + (wo >> 1)]; // row 2ho+1
                s0[j] = e ? r0.z : r0.x;
                s1[j] = e ? r0.w : r0.y;
                s2[j] = e ? r1.z : r1.x;
                s3[j] = e ? r1.w : r1.y;
            }
            const float inv = 1.0f / (float)Cm;
            const float w0 = (float)( cc        & 255u) * inv;
            const float w1 = (float)((cc >>  8) & 255u) * inv;
            const float w2 = (float)((cc >> 16) & 255u) * inv;
            const float w3 = (float)((cc >> 24) & 255u) * inv;

            const float mean0 = s0[0]*w0 + s1[0]*w1 + s2[0]*w2 + s3[0]*w3;
            const float mean1 = s0[1]*w0 + s1[1]*w1 + s2[1]*w2 + s3[1]*w3;

            float var0 = s0[2]*w0 + s1[2]*w1 + s2[2]*w2 + s3[2]*w3;
            float var1 = s0[3]*w0 + s1[3]*w1 + s2[3]*w2 + s3[3]*w3;
            float cov  = s0[4]*w0 + s1[4]*w1 + s2[4]*w2 + s3[4]*w3;

            const float d00 = s0[0]-mean0, d10 = s1[0]-mean0, d20 = s2[0]-mean0, d30 = s3[0]-mean0;
            const float d01 = s0[1]-mean1, d11 = s1[1]-mean1, d21 = s2[1]-mean1, d31 = s3[1]-mean1;
            var0 += d00*d00*w0 + d10*d10*w1 + d20*d20*w2 + d30*d30*w3;
            var1 += d01*d01*w0 + d11*d11*w1 + d21*d21*w2 + d31*d31*w3;
            cov  += d00*d01*w0 + d10*d11*w1 + d20*d21*w2 + d30*d31*w3;

            const size_t base = (size_t)Cm * HoWo + ho * Wo + wo;
            ob[base           ] = mean0;
            ob[base +     HoWo] = mean1;
            ob[base + 2 * HoWo] = var0;
            ob[base + 3 * HoWo] = var1;
            ob[base + 4 * HoWo] = cov;
        }

        tile = next_tile;
        par ^= 1;
    }

    // ---- self-reset for the next graph replay (last block restores state)
    if (threadIdx.x == 0) {
        __threadfence();                          // order prior atomics/stores
        int d = atomicAdd(&g_done, 1);
        if (d == NBLOCKS - 1) {
            g_ticket = NBLOCKS;
            g_done   = 0;
        }
    }
}

extern "C" void kernel_launch(void* const* d_in, const int* in_sizes, int n_in,
                              void* d_out, int out_size) {
    const float* x = (const float*)d_in[0];
    float* out = (float*)d_out;
    spatial_maxpool_stats_kernel<<<NBLOCKS, NWARPS * 32>>>(x, out);
}